// round 2
// baseline (speedup 1.0000x reference)
#include <cuda_runtime.h>
#include <math.h>

#define V_N 100000
#define E_N 1600000
#define LN_N 64
#define S_N 8
#define NET 10
// MU/S = 0.9/8
#define MU_OVER_S 0.1125f

// ---------------- device scratch (static, no allocation) ----------------
__device__ float P_buf[(size_t)V_N * 128];   // per-node: [0:64) node-part proj, [64:128) neis-part proj
__device__ float Q_buf[(size_t)V_N * 8];     // per-node: W_rou projection
__device__ float A_buf[(size_t)E_N * 64];    // per-edge transition matrices (i*8+j)
__device__ float B_buf[(size_t)E_N * 8];     // per-edge bias
__device__ float Hbuf[2 * (size_t)V_N * 8];  // ping-pong node state
__device__ float logits_buf[V_N];
__device__ float blkmax_buf[256];
__device__ float g_max;
__device__ float g_acc[9];                   // [0]=Z, [1..8]=weighted sums
__device__ int   g_idx64;                    // 1 if index arrays are int64

// ---------------- index dtype detection (int64 vs int32) ----------------
__global__ void detect_kernel(const unsigned int* __restrict__ x) {
    if (threadIdx.x == 0 && blockIdx.x == 0) {
        int all0 = 1;
        // values are in [1, V]; if stored as little-endian int64, every odd dword is 0.
        for (int i = 1; i < 128; i += 2) all0 &= (x[i] == 0u);
        g_idx64 = all0;
    }
}

__device__ __forceinline__ int load_idx(const void* p, int e) {
    if (g_idx64) return (int)((const long long*)p)[e];
    return ((const int*)p)[e];
}

// ---------------- per-node projection: P1, P2, Q ----------------
// feat [V,64]; W_xi [64,138] row-major; W_rou [8,64]
__global__ void proj_kernel(const float* __restrict__ feat,
                            const float* __restrict__ W_xi,
                            const float* __restrict__ W_rou) {
    __shared__ float2 Wn2[64 * 32];  // Wn2[k*32+l] = (W_xi[2l][k], W_xi[2l+1][k])
    __shared__ float2 Wm2[64 * 32];  // same with k offset 64 (neis part)
    __shared__ float  Wr[64 * 8];    // Wr[k*8+s] = W_rou[s][k]
    __shared__ float  xs[4][64];

    int tid = threadIdx.x;
    for (int idx = tid; idx < 2048; idx += blockDim.x) {
        int k = idx >> 5, l = idx & 31;
        Wn2[idx] = make_float2(W_xi[(2 * l) * 138 + k],      W_xi[(2 * l + 1) * 138 + k]);
        Wm2[idx] = make_float2(W_xi[(2 * l) * 138 + 64 + k], W_xi[(2 * l + 1) * 138 + 64 + k]);
    }
    for (int idx = tid; idx < 512; idx += blockDim.x) {
        int k = idx >> 3, s = idx & 7;
        Wr[idx] = W_rou[s * 64 + k];
    }
    __syncthreads();

    int w = tid >> 5, lane = tid & 31;
    int warpGlobal = blockIdx.x * 4 + w;
    int nWarps = gridDim.x * 4;
    for (int v = warpGlobal; v < V_N; v += nWarps) {
        xs[w][lane]      = feat[(size_t)v * 64 + lane];
        xs[w][32 + lane] = feat[(size_t)v * 64 + 32 + lane];
        __syncwarp();
        float2 an = make_float2(0.f, 0.f), am = make_float2(0.f, 0.f);
        float aq = 0.f;
#pragma unroll 8
        for (int k = 0; k < 64; k++) {
            float x = xs[w][k];
            float2 wn = Wn2[k * 32 + lane];
            float2 wm = Wm2[k * 32 + lane];
            an.x += x * wn.x; an.y += x * wn.y;
            am.x += x * wm.x; am.y += x * wm.y;
            if (lane < 8) aq += x * Wr[k * 8 + lane];
        }
        ((float2*)(P_buf + (size_t)v * 128))[lane]      = an;
        ((float2*)(P_buf + (size_t)v * 128 + 64))[lane] = am;
        if (lane < 8) Q_buf[(size_t)v * 8 + lane] = aq;
        __syncwarp();
    }
}

// ---------------- per-edge A and bias precompute ----------------
// thread t handles (edge e = gid/8, row r = gid%8): 8 A entries + 1 bias entry
__global__ void edge_pre_kernel(const void* __restrict__ Xn,
                                const void* __restrict__ Xe,
                                const int* __restrict__ etype,
                                const float* __restrict__ dg,
                                const float* __restrict__ W_xi,
                                const float* __restrict__ b_xi,
                                const float* __restrict__ b_rou) {
    __shared__ float4 Cet4[160];  // Cet[t][o] = W_xi[o][128+t] + b_xi[o]
    __shared__ float  brs[8];
    float* Cet = (float*)Cet4;
    int tid = threadIdx.x;
    for (int idx = tid; idx < 640; idx += blockDim.x) {
        int t = idx >> 6, o = idx & 63;
        Cet[idx] = W_xi[o * 138 + 128 + t] + b_xi[o];
    }
    if (tid < 8) brs[tid] = b_rou[tid];
    __syncthreads();

    long long gid = (long long)blockIdx.x * blockDim.x + tid;
    int e = (int)(gid >> 3), r = (int)(gid & 7);
    if (e >= E_N) return;

    int src = load_idx(Xn, e) - 1;
    int de  = load_idx(Xe, e) - 1;
    int et  = etype[e] - 1;
    float scale = MU_OVER_S / dg[e];

    const float4* p1 = (const float4*)(P_buf + (size_t)src * 128 + r * 8);
    const float4* p2 = (const float4*)(P_buf + (size_t)de * 128 + 64 + r * 8);
    const float4* c4 = (const float4*)(Cet + et * 64 + r * 8);
    float4 pa0 = p1[0], pa1 = p1[1];
    float4 pb0 = p2[0], pb1 = p2[1];
    float4 c0 = c4[0], c1 = c4[1];

    float4 o0, o1;
    o0.x = tanhf(pa0.x + pb0.x + c0.x) * scale;
    o0.y = tanhf(pa0.y + pb0.y + c0.y) * scale;
    o0.z = tanhf(pa0.z + pb0.z + c0.z) * scale;
    o0.w = tanhf(pa0.w + pb0.w + c0.w) * scale;
    o1.x = tanhf(pa1.x + pb1.x + c1.x) * scale;
    o1.y = tanhf(pa1.y + pb1.y + c1.y) * scale;
    o1.z = tanhf(pa1.z + pb1.z + c1.z) * scale;
    o1.w = tanhf(pa1.w + pb1.w + c1.w) * scale;

    float4* Aout = (float4*)(A_buf + (size_t)e * 64 + r * 8);
    Aout[0] = o0; Aout[1] = o1;

    B_buf[(size_t)e * 8 + r] = tanhf(Q_buf[(size_t)de * 8 + r] + brs[r]);
}

// ---------------- zero H buffer ----------------
__global__ void zero_kernel(float* __restrict__ p, int n4) {
    int i = blockIdx.x * blockDim.x + threadIdx.x;
    if (i < n4) ((float4*)p)[i] = make_float4(0.f, 0.f, 0.f, 0.f);
}

// ---------------- one recurrence step ----------------
__global__ void step_kernel(const void* __restrict__ Xn,
                            const void* __restrict__ Xe,
                            const float* __restrict__ Hcur,
                            float* __restrict__ Hnext) {
    long long gid = (long long)blockIdx.x * blockDim.x + threadIdx.x;
    int e = (int)(gid >> 3), r = (int)(gid & 7);
    if (e >= E_N) return;

    int src  = load_idx(Xn, e) - 1;
    int draw = load_idx(Xe, e);  // RAW 1-indexed scatter id (reference semantics)

    const float4* A4 = (const float4*)(A_buf + (size_t)e * 64 + r * 8);
    float4 a0 = A4[0], a1 = A4[1];
    const float4* H4 = (const float4*)(Hcur + (size_t)src * 8);
    float4 h0 = H4[0], h1 = H4[1];

    float out = a0.x * h0.x + a0.y * h0.y + a0.z * h0.z + a0.w * h0.w
              + a1.x * h1.x + a1.y * h1.y + a1.z * h1.z + a1.w * h1.w
              + B_buf[(size_t)e * 8 + r];

    if (draw < V_N) atomicAdd(&Hnext[(size_t)draw * 8 + r], out);
}

// ---------------- readout ----------------
__global__ void logits_kernel(const float* __restrict__ H,
                              const float* __restrict__ W1,
                              const float* __restrict__ b1) {
    __shared__ float sm[256];
    __shared__ float w[8];
    int tid = threadIdx.x;
    if (tid < 8) w[tid] = W1[tid];
    __syncthreads();
    float bb = b1[0];
    float lmax = -1e30f;
    for (int v = blockIdx.x * blockDim.x + tid; v < V_N; v += gridDim.x * blockDim.x) {
        const float4* h4 = (const float4*)(H + (size_t)v * 8);
        float4 h0 = h4[0], h1 = h4[1];
        float l = h0.x * w[0] + h0.y * w[1] + h0.z * w[2] + h0.w * w[3]
                + h1.x * w[4] + h1.y * w[5] + h1.z * w[6] + h1.w * w[7] + bb;
        logits_buf[v] = l;
        lmax = fmaxf(lmax, l);
    }
    sm[tid] = lmax;
    __syncthreads();
    for (int s = 128; s; s >>= 1) {
        if (tid < s) sm[tid] = fmaxf(sm[tid], sm[tid + s]);
        __syncthreads();
    }
    if (tid == 0) blkmax_buf[blockIdx.x] = sm[0];
}

__global__ void reduce_max_kernel() {
    __shared__ float sm[256];
    int tid = threadIdx.x;
    sm[tid] = blkmax_buf[tid];
    __syncthreads();
    for (int s = 128; s; s >>= 1) {
        if (tid < s) sm[tid] = fmaxf(sm[tid], sm[tid + s]);
        __syncthreads();
    }
    if (tid == 0) g_max = sm[0];
    if (tid < 9) g_acc[tid] = 0.f;
}

__global__ void smacc_kernel(const float* __restrict__ H) {
    __shared__ float sm[256];
    int tid = threadIdx.x;
    float gm = g_max;
    float z = 0.f, s0 = 0.f, s1 = 0.f, s2 = 0.f, s3 = 0.f, s4 = 0.f, s5 = 0.f, s6 = 0.f, s7 = 0.f;
    for (int v = blockIdx.x * blockDim.x + tid; v < V_N; v += gridDim.x * blockDim.x) {
        float wv = expf(logits_buf[v] - gm);
        const float4* h4 = (const float4*)(H + (size_t)v * 8);
        float4 h0 = h4[0], h1 = h4[1];
        z += wv;
        s0 += wv * h0.x; s1 += wv * h0.y; s2 += wv * h0.z; s3 += wv * h0.w;
        s4 += wv * h1.x; s5 += wv * h1.y; s6 += wv * h1.z; s7 += wv * h1.w;
    }
    float vals[9] = {z, s0, s1, s2, s3, s4, s5, s6, s7};
#pragma unroll
    for (int j = 0; j < 9; j++) {
        sm[tid] = vals[j];
        __syncthreads();
        for (int s = 128; s; s >>= 1) {
            if (tid < s) sm[tid] += sm[tid + s];
            __syncthreads();
        }
        if (tid == 0) atomicAdd(&g_acc[j], sm[0]);
        __syncthreads();
    }
}

__global__ void final_kernel(float* __restrict__ out) {
    if (threadIdx.x < 8) out[threadIdx.x] = tanhf(g_acc[1 + threadIdx.x] / g_acc[0]);
}

// ---------------- launch ----------------
extern "C" void kernel_launch(void* const* d_in, const int* in_sizes, int n_in,
                              void* d_out, int out_size) {
    const float* feat  = (const float*)d_in[0];
    const void*  Xn    = d_in[1];
    const void*  Xe    = d_in[2];
    const int*   etype = (const int*)d_in[3];
    const float* dg    = (const float*)d_in[4];
    const float* Hinit = (const float*)d_in[5];
    const float* Wxi   = (const float*)d_in[6];
    const float* bxi   = (const float*)d_in[7];
    const float* Wrou  = (const float*)d_in[8];
    const float* brou  = (const float*)d_in[9];
    const float* W1    = (const float*)d_in[10];
    const float* b1    = (const float*)d_in[11];
    float* out = (float*)d_out;

    float* H;
    cudaGetSymbolAddress((void**)&H, Hbuf);
    float* H0 = H;
    float* H1 = H + (size_t)V_N * 8;

    const int EBLK = (E_N * 8 + 255) / 256;      // 50000 blocks, 256 threads
    const int HN4  = V_N * 8 / 4;                // float4 count for zeroing
    const int ZBLK = (HN4 + 255) / 256;

    detect_kernel<<<1, 32>>>((const unsigned int*)Xn);
    proj_kernel<<<512, 128>>>(feat, Wxi, Wrou);
    edge_pre_kernel<<<EBLK, 256>>>(Xn, Xe, etype, dg, Wxi, bxi, brou);

    // T = 4 recurrence steps (ping-pong H0/H1), Hnext zeroed each step
    zero_kernel<<<ZBLK, 256>>>(H0, HN4);
    step_kernel<<<EBLK, 256>>>(Xn, Xe, Hinit, H0);
    zero_kernel<<<ZBLK, 256>>>(H1, HN4);
    step_kernel<<<EBLK, 256>>>(Xn, Xe, H0, H1);
    zero_kernel<<<ZBLK, 256>>>(H0, HN4);
    step_kernel<<<EBLK, 256>>>(Xn, Xe, H1, H0);
    zero_kernel<<<ZBLK, 256>>>(H1, HN4);
    step_kernel<<<EBLK, 256>>>(Xn, Xe, H0, H1);

    logits_kernel<<<256, 256>>>(H1, W1, b1);
    reduce_max_kernel<<<1, 256>>>();
    smacc_kernel<<<256, 256>>>(H1);
    final_kernel<<<1, 32>>>(out);
}

// round 3
// speedup vs baseline: 1.2269x; 1.2269x over previous
#include <cuda_runtime.h>
#include <cuda_fp16.h>
#include <math.h>

#define V_N 100000
#define E_N 1600000
#define LN_N 64
#define S_N 8
#define NET 10
// MU/S = 0.9/8
#define MU_OVER_S 0.1125f

// ---------------- device scratch (static, no allocation) ----------------
__device__ float  P_buf[(size_t)V_N * 128];   // per-node: [0:64) node-part proj, [64:128) neis-part proj
__device__ float  Q_buf[(size_t)V_N * 8];     // per-node: W_rou projection
__device__ __half A_buf[(size_t)E_N * 64];    // per-edge transition matrices (i*8+j), fp16
__device__ __half B_buf[(size_t)E_N * 8];     // per-edge bias, fp16
__device__ float  Hbuf[2 * (size_t)V_N * 8];  // ping-pong node state
__device__ float  logits_buf[V_N];
__device__ float  blkmax_buf[256];
__device__ float  g_max;
__device__ float  g_acc[9];                   // [0]=Z, [1..8]=weighted sums
__device__ int    g_idx64;                    // 1 if index arrays are int64

__device__ __forceinline__ float tanh_fast(float x) {
    float y;
    asm("tanh.approx.f32 %0, %1;" : "=f"(y) : "f"(x));
    return y;
}

// ---------------- index dtype detection (int64 vs int32) ----------------
__global__ void detect_kernel(const unsigned int* __restrict__ x) {
    if (threadIdx.x == 0 && blockIdx.x == 0) {
        int all0 = 1;
        // values are in [1, V]; if stored as little-endian int64, every odd dword is 0.
        for (int i = 1; i < 128; i += 2) all0 &= (x[i] == 0u);
        g_idx64 = all0;
    }
}

__device__ __forceinline__ int load_idx(const void* p, int e) {
    if (g_idx64) return (int)((const long long*)p)[e];
    return ((const int*)p)[e];
}

// ---------------- per-node projection: P1, P2, Q ----------------
// feat [V,64]; W_xi [64,138] row-major; W_rou [8,64]
__global__ void proj_kernel(const float* __restrict__ feat,
                            const float* __restrict__ W_xi,
                            const float* __restrict__ W_rou) {
    __shared__ float2 Wn2[64 * 32];  // Wn2[k*32+l] = (W_xi[2l][k], W_xi[2l+1][k])
    __shared__ float2 Wm2[64 * 32];  // same with k offset 64 (neis part)
    __shared__ float  Wr[64 * 8];    // Wr[k*8+s] = W_rou[s][k]
    __shared__ float  xs[4][64];

    int tid = threadIdx.x;
    for (int idx = tid; idx < 2048; idx += blockDim.x) {
        int k = idx >> 5, l = idx & 31;
        Wn2[idx] = make_float2(W_xi[(2 * l) * 138 + k],      W_xi[(2 * l + 1) * 138 + k]);
        Wm2[idx] = make_float2(W_xi[(2 * l) * 138 + 64 + k], W_xi[(2 * l + 1) * 138 + 64 + k]);
    }
    for (int idx = tid; idx < 512; idx += blockDim.x) {
        int k = idx >> 3, s = idx & 7;
        Wr[idx] = W_rou[s * 64 + k];
    }
    __syncthreads();

    int w = tid >> 5, lane = tid & 31;
    int warpGlobal = blockIdx.x * 4 + w;
    int nWarps = gridDim.x * 4;
    for (int v = warpGlobal; v < V_N; v += nWarps) {
        xs[w][lane]      = feat[(size_t)v * 64 + lane];
        xs[w][32 + lane] = feat[(size_t)v * 64 + 32 + lane];
        __syncwarp();
        float2 an = make_float2(0.f, 0.f), am = make_float2(0.f, 0.f);
        float aq = 0.f;
#pragma unroll 8
        for (int k = 0; k < 64; k++) {
            float x = xs[w][k];
            float2 wn = Wn2[k * 32 + lane];
            float2 wm = Wm2[k * 32 + lane];
            an.x += x * wn.x; an.y += x * wn.y;
            am.x += x * wm.x; am.y += x * wm.y;
            if (lane < 8) aq += x * Wr[k * 8 + lane];
        }
        ((float2*)(P_buf + (size_t)v * 128))[lane]      = an;
        ((float2*)(P_buf + (size_t)v * 128 + 64))[lane] = am;
        if (lane < 8) Q_buf[(size_t)v * 8 + lane] = aq;
        __syncwarp();
    }
}

// ---------------- per-edge A and bias precompute ----------------
// thread t handles (edge e = gid/8, row r = gid%8): 8 A entries + 1 bias entry
__global__ void edge_pre_kernel(const void* __restrict__ Xn,
                                const void* __restrict__ Xe,
                                const int* __restrict__ etype,
                                const float* __restrict__ dg,
                                const float* __restrict__ W_xi,
                                const float* __restrict__ b_xi,
                                const float* __restrict__ b_rou) {
    __shared__ float4 Cet4[160];  // Cet[t][o] = W_xi[o][128+t] + b_xi[o]
    __shared__ float  brs[8];
    float* Cet = (float*)Cet4;
    int tid = threadIdx.x;
    for (int idx = tid; idx < 640; idx += blockDim.x) {
        int t = idx >> 6, o = idx & 63;
        Cet[idx] = W_xi[o * 138 + 128 + t] + b_xi[o];
    }
    if (tid < 8) brs[tid] = b_rou[tid];
    __syncthreads();

    long long gid = (long long)blockIdx.x * blockDim.x + tid;
    int e = (int)(gid >> 3), r = (int)(gid & 7);
    if (e >= E_N) return;

    int src = load_idx(Xn, e) - 1;
    int de  = load_idx(Xe, e) - 1;
    int et  = etype[e] - 1;
    float scale = MU_OVER_S / dg[e];

    const float4* p1 = (const float4*)(P_buf + (size_t)src * 128 + r * 8);
    const float4* p2 = (const float4*)(P_buf + (size_t)de * 128 + 64 + r * 8);
    const float4* c4 = (const float4*)(Cet + et * 64 + r * 8);
    float4 pa0 = p1[0], pa1 = p1[1];
    float4 pb0 = p2[0], pb1 = p2[1];
    float4 c0 = c4[0], c1 = c4[1];

    float4 o0, o1;
    o0.x = tanh_fast(pa0.x + pb0.x + c0.x) * scale;
    o0.y = tanh_fast(pa0.y + pb0.y + c0.y) * scale;
    o0.z = tanh_fast(pa0.z + pb0.z + c0.z) * scale;
    o0.w = tanh_fast(pa0.w + pb0.w + c0.w) * scale;
    o1.x = tanh_fast(pa1.x + pb1.x + c1.x) * scale;
    o1.y = tanh_fast(pa1.y + pb1.y + c1.y) * scale;
    o1.z = tanh_fast(pa1.z + pb1.z + c1.z) * scale;
    o1.w = tanh_fast(pa1.w + pb1.w + c1.w) * scale;

    // pack 8 fp16 values into one 16B store
    __half2 h[4];
    h[0] = __floats2half2_rn(o0.x, o0.y);
    h[1] = __floats2half2_rn(o0.z, o0.w);
    h[2] = __floats2half2_rn(o1.x, o1.y);
    h[3] = __floats2half2_rn(o1.z, o1.w);
    *(uint4*)(A_buf + (size_t)e * 64 + r * 8) = *(const uint4*)h;

    B_buf[(size_t)e * 8 + r] = __float2half_rn(tanhf(Q_buf[(size_t)de * 8 + r] + brs[r]));
}

// ---------------- zero H buffer ----------------
__global__ void zero_kernel(float* __restrict__ p, int n4) {
    int i = blockIdx.x * blockDim.x + threadIdx.x;
    if (i < n4) ((float4*)p)[i] = make_float4(0.f, 0.f, 0.f, 0.f);
}

// ---------------- one recurrence step ----------------
__global__ void step_kernel(const void* __restrict__ Xn,
                            const void* __restrict__ Xe,
                            const float* __restrict__ Hcur,
                            float* __restrict__ Hnext) {
    long long gid = (long long)blockIdx.x * blockDim.x + threadIdx.x;
    int e = (int)(gid >> 3), r = (int)(gid & 7);
    if (e >= E_N) return;

    int src  = load_idx(Xn, e) - 1;
    int draw = load_idx(Xe, e);  // RAW 1-indexed scatter id (reference semantics)

    uint4 araw = *(const uint4*)(A_buf + (size_t)e * 64 + r * 8);
    const __half2* ah = (const __half2*)&araw;
    float2 a0 = __half22float2(ah[0]);
    float2 a1 = __half22float2(ah[1]);
    float2 a2 = __half22float2(ah[2]);
    float2 a3 = __half22float2(ah[3]);

    const float4* H4 = (const float4*)(Hcur + (size_t)src * 8);
    float4 h0 = H4[0], h1 = H4[1];

    float out = a0.x * h0.x + a0.y * h0.y + a1.x * h0.z + a1.y * h0.w
              + a2.x * h1.x + a2.y * h1.y + a3.x * h1.z + a3.y * h1.w
              + __half2float(B_buf[(size_t)e * 8 + r]);

    if (draw < V_N) atomicAdd(&Hnext[(size_t)draw * 8 + r], out);
}

// ---------------- readout ----------------
__global__ void logits_kernel(const float* __restrict__ H,
                              const float* __restrict__ W1,
                              const float* __restrict__ b1) {
    __shared__ float sm[256];
    __shared__ float w[8];
    int tid = threadIdx.x;
    if (tid < 8) w[tid] = W1[tid];
    __syncthreads();
    float bb = b1[0];
    float lmax = -1e30f;
    for (int v = blockIdx.x * blockDim.x + tid; v < V_N; v += gridDim.x * blockDim.x) {
        const float4* h4 = (const float4*)(H + (size_t)v * 8);
        float4 h0 = h4[0], h1 = h4[1];
        float l = h0.x * w[0] + h0.y * w[1] + h0.z * w[2] + h0.w * w[3]
                + h1.x * w[4] + h1.y * w[5] + h1.z * w[6] + h1.w * w[7] + bb;
        logits_buf[v] = l;
        lmax = fmaxf(lmax, l);
    }
    sm[tid] = lmax;
    __syncthreads();
    for (int s = 128; s; s >>= 1) {
        if (tid < s) sm[tid] = fmaxf(sm[tid], sm[tid + s]);
        __syncthreads();
    }
    if (tid == 0) blkmax_buf[blockIdx.x] = sm[0];
}

__global__ void reduce_max_kernel() {
    __shared__ float sm[256];
    int tid = threadIdx.x;
    sm[tid] = blkmax_buf[tid];
    __syncthreads();
    for (int s = 128; s; s >>= 1) {
        if (tid < s) sm[tid] = fmaxf(sm[tid], sm[tid + s]);
        __syncthreads();
    }
    if (tid == 0) g_max = sm[0];
    if (tid < 9) g_acc[tid] = 0.f;
}

__global__ void smacc_kernel(const float* __restrict__ H) {
    __shared__ float sm[256];
    int tid = threadIdx.x;
    float gm = g_max;
    float z = 0.f, s0 = 0.f, s1 = 0.f, s2 = 0.f, s3 = 0.f, s4 = 0.f, s5 = 0.f, s6 = 0.f, s7 = 0.f;
    for (int v = blockIdx.x * blockDim.x + tid; v < V_N; v += gridDim.x * blockDim.x) {
        float wv = expf(logits_buf[v] - gm);
        const float4* h4 = (const float4*)(H + (size_t)v * 8);
        float4 h0 = h4[0], h1 = h4[1];
        z += wv;
        s0 += wv * h0.x; s1 += wv * h0.y; s2 += wv * h0.z; s3 += wv * h0.w;
        s4 += wv * h1.x; s5 += wv * h1.y; s6 += wv * h1.z; s7 += wv * h1.w;
    }
    float vals[9] = {z, s0, s1, s2, s3, s4, s5, s6, s7};
#pragma unroll
    for (int j = 0; j < 9; j++) {
        sm[tid] = vals[j];
        __syncthreads();
        for (int s = 128; s; s >>= 1) {
            if (tid < s) sm[tid] += sm[tid + s];
            __syncthreads();
        }
        if (tid == 0) atomicAdd(&g_acc[j], sm[0]);
        __syncthreads();
    }
}

__global__ void final_kernel(float* __restrict__ out) {
    if (threadIdx.x < 8) out[threadIdx.x] = tanhf(g_acc[1 + threadIdx.x] / g_acc[0]);
}

// ---------------- launch ----------------
extern "C" void kernel_launch(void* const* d_in, const int* in_sizes, int n_in,
                              void* d_out, int out_size) {
    const float* feat  = (const float*)d_in[0];
    const void*  Xn    = d_in[1];
    const void*  Xe    = d_in[2];
    const int*   etype = (const int*)d_in[3];
    const float* dg    = (const float*)d_in[4];
    const float* Hinit = (const float*)d_in[5];
    const float* Wxi   = (const float*)d_in[6];
    const float* bxi   = (const float*)d_in[7];
    const float* Wrou  = (const float*)d_in[8];
    const float* brou  = (const float*)d_in[9];
    const float* W1    = (const float*)d_in[10];
    const float* b1    = (const float*)d_in[11];
    float* out = (float*)d_out;

    float* H;
    cudaGetSymbolAddress((void**)&H, Hbuf);
    float* H0 = H;
    float* H1 = H + (size_t)V_N * 8;

    const int EBLK = (E_N * 8 + 255) / 256;      // 50000 blocks, 256 threads
    const int HN4  = V_N * 8 / 4;                // float4 count for zeroing
    const int ZBLK = (HN4 + 255) / 256;

    detect_kernel<<<1, 32>>>((const unsigned int*)Xn);
    proj_kernel<<<512, 128>>>(feat, Wxi, Wrou);
    edge_pre_kernel<<<EBLK, 256>>>(Xn, Xe, etype, dg, Wxi, bxi, brou);

    // T = 4 recurrence steps (ping-pong H0/H1), Hnext zeroed each step
    zero_kernel<<<ZBLK, 256>>>(H0, HN4);
    step_kernel<<<EBLK, 256>>>(Xn, Xe, Hinit, H0);
    zero_kernel<<<ZBLK, 256>>>(H1, HN4);
    step_kernel<<<EBLK, 256>>>(Xn, Xe, H0, H1);
    zero_kernel<<<ZBLK, 256>>>(H0, HN4);
    step_kernel<<<EBLK, 256>>>(Xn, Xe, H1, H0);
    zero_kernel<<<ZBLK, 256>>>(H1, HN4);
    step_kernel<<<EBLK, 256>>>(Xn, Xe, H0, H1);

    logits_kernel<<<256, 256>>>(H1, W1, b1);
    reduce_max_kernel<<<1, 256>>>();
    smacc_kernel<<<256, 256>>>(H1);
    final_kernel<<<1, 32>>>(out);
}